// round 3
// baseline (speedup 1.0000x reference)
#include <cuda_runtime.h>
#include <math.h>

// Problem constants
#define B_  4
#define N_  2048
#define E_  512
#define H_  8
#define D_  64
#define BH_ 32   // B_*H_

// ---------------- scratch (static __device__; no allocations allowed) -------
__device__ float g_xT [B_ * E_ * N_];   // [b][e][n]
__device__ float g_WkT[E_ * E_];        // [e][hd]
__device__ float g_WvT[E_ * E_];        // [e][hd]
__device__ float g_KT [BH_ * D_ * N_];  // [bh][d][n]  (keys, transposed)
__device__ float g_V  [BH_ * N_ * D_];  // [bh][n][d]  (values, natural)

// ---------------- generic batched 32x32 tiled transpose ---------------------
// dst[c][r] = src[r][c], src is R x C. All dims here divide 32.
__global__ void transpose_k(const float* __restrict__ src,
                            float* __restrict__ dst, int R, int C) {
    __shared__ float t[32][33];
    size_t off = (size_t)blockIdx.z * R * C;
    src += off; dst += off;
    int c0 = blockIdx.x * 32, r0 = blockIdx.y * 32;
#pragma unroll
    for (int i = threadIdx.y; i < 32; i += 8)
        t[i][threadIdx.x] = src[(size_t)(r0 + i) * C + c0 + threadIdx.x];
    __syncthreads();
#pragma unroll
    for (int i = threadIdx.y; i < 32; i += 8)
        dst[(size_t)(c0 + i) * R + r0 + threadIdx.x] = t[threadIdx.x][i];
}

// ---------------- K/V projection GEMM ---------------------------------------
// out[m, hd] = sum_e x[m, e] * W[hd, e] + bias[hd], m = (b, n)
// blockIdx.z == 0 -> K (written transposed to g_KT[bh][d][n])
// blockIdx.z == 1 -> V (written natural to g_V[bh][n][d])
// Tile: 64 rows (n) x 64 cols (hd = h*64 + d, one head per CTA in y).
// 128 threads (16 tx x 8 ty), 8x4 microtile: rows 8*ty+i, cols 4*tx+j.
// Dynamic smem: xs[64][64] + ws[64][64] = 32 KB.
__global__ void __launch_bounds__(128) proj_kernel(const float* __restrict__ bk,
                                                   const float* __restrict__ bv) {
    extern __shared__ float sm[];
    float* xs = sm;              // [64 e][64 rows]
    float* ws = sm + 64 * 64;    // [64 e][64 cols]

    int tid = threadIdx.x;
    int tx = tid & 15, ty = tid >> 4;          // 16 x 8
    int m0 = blockIdx.x * 64;                  // 128 row-tiles over B*N = 8192
    int b  = m0 >> 11;
    int n0 = m0 & 2047;
    int h  = blockIdx.y;                       // 0..7
    int c0 = h * 64;
    int z  = blockIdx.z;
    const float* WT = z ? g_WvT : g_WkT;

    float acc[8][4];
#pragma unroll
    for (int i = 0; i < 8; i++)
#pragma unroll
        for (int j = 0; j < 4; j++) acc[i][j] = 0.f;

    for (int ec = 0; ec < 8; ec++) {
        int e0 = ec * 64;
        __syncthreads();
#pragma unroll
        for (int it = 0; it < 8; it++) {        // xs: 64x64 = 1024 float4
            int idx = it * 128 + tid;
            int e = idx >> 4, cc = idx & 15;
            *(float4*)&xs[e * 64 + cc * 4] =
                *(const float4*)&g_xT[((size_t)b * E_ + e0 + e) * N_ + n0 + cc * 4];
        }
#pragma unroll
        for (int it = 0; it < 8; it++) {        // ws: 64x64 = 1024 float4
            int idx = it * 128 + tid;
            int e = idx >> 4, cc = idx & 15;
            *(float4*)&ws[e * 64 + cc * 4] =
                *(const float4*)&WT[(size_t)(e0 + e) * E_ + c0 + cc * 4];
        }
        __syncthreads();
#pragma unroll 8
        for (int e = 0; e < 64; e++) {
            float4 xa = *(float4*)&xs[e * 64 + 8 * ty];
            float4 xb = *(float4*)&xs[e * 64 + 8 * ty + 4];
            float4 w  = *(float4*)&ws[e * 64 + 4 * tx];
            float xv[8] = {xa.x, xa.y, xa.z, xa.w, xb.x, xb.y, xb.z, xb.w};
            float wv[4] = {w.x, w.y, w.z, w.w};
#pragma unroll
            for (int i = 0; i < 8; i++)
#pragma unroll
                for (int j = 0; j < 4; j++) acc[i][j] += xv[i] * wv[j];
        }
    }

    const float* bias = z ? bv : bk;
    float bb[4];
#pragma unroll
    for (int j = 0; j < 4; j++) bb[j] = bias[c0 + 4 * tx + j];

    int bh = b * 8 + h;
#pragma unroll
    for (int i = 0; i < 8; i++) {
        int n = n0 + 8 * ty + i;
        if (z == 0) {
#pragma unroll
            for (int j = 0; j < 4; j++)
                g_KT[((size_t)bh * 64 + 4 * tx + j) * N_ + n] = acc[i][j] + bb[j];
        } else {
            float4 v = make_float4(acc[i][0] + bb[0], acc[i][1] + bb[1],
                                   acc[i][2] + bb[2], acc[i][3] + bb[3]);
            *(float4*)&g_V[((size_t)bh * N_ + n) * 64 + 4 * tx] = v;
        }
    }
}

// ---------------- flash attention (Q == K) -----------------------------------
// Per CTA: one (bh, 64-query tile). Loop over 16 key tiles of 128.
// 128 threads (16 tx x 8 ty). S microtile 8x8, O microtile 8 rows x 4 dims.
// Dynamic smem: Qs[64][64] + Ks[64][128] + Vs[128][64] + Ps[64][128] = 112 KB.
__global__ void __launch_bounds__(128) attn_kernel(float* __restrict__ out) {
    extern __shared__ float sm[];
    float* Qs = sm;                        // [d][qrow]   64x64
    float* Ks = sm + 4096;                 // [d][key]    64x128
    float* Vs = sm + 4096 + 8192;          // [key][dim]  128x64
    float* Ps = sm + 4096 + 8192 + 8192;   // [qrow][key] 64x128

    int tid = threadIdx.x;
    int tx = tid & 15, ty = tid >> 4;
    int q0 = blockIdx.x * 64;
    int bh = blockIdx.y;
    const float* KTb = g_KT + (size_t)bh * D_ * N_;
    const float* Vb  = g_V  + (size_t)bh * N_ * D_;

    // load Q tile (transposed layout: Qs[d][qrow])
#pragma unroll
    for (int it = 0; it < 8; it++) {
        int idx = it * 128 + tid;
        int d = idx >> 4, cc = idx & 15;
        *(float4*)&Qs[d * 64 + cc * 4] =
            *(const float4*)&KTb[(size_t)d * N_ + q0 + cc * 4];
    }

    float m[8], l[8], O[8][4];
#pragma unroll
    for (int i = 0; i < 8; i++) {
        m[i] = -1e30f; l[i] = 0.f;
#pragma unroll
        for (int j = 0; j < 4; j++) O[i][j] = 0.f;
    }

    for (int kt = 0; kt < 16; kt++) {
        int k0 = kt * 128;
        __syncthreads();   // previous O-GEMM finished with Ks/Vs/Ps
#pragma unroll
        for (int it = 0; it < 16; it++) {   // Ks: 64x128
            int idx = it * 128 + tid;
            int d = idx >> 5, cc = idx & 31;
            *(float4*)&Ks[d * 128 + cc * 4] =
                *(const float4*)&KTb[(size_t)d * N_ + k0 + cc * 4];
        }
#pragma unroll
        for (int it = 0; it < 16; it++) {   // Vs: 128x64
            int idx = it * 128 + tid;
            int k = idx >> 4, cc = idx & 15;
            *(float4*)&Vs[k * 64 + cc * 4] =
                *(const float4*)&Vb[(size_t)(k0 + k) * 64 + cc * 4];
        }
        __syncthreads();

        // S = Q @ K^T  (8x8 per thread)
        float acc[8][8];
#pragma unroll
        for (int i = 0; i < 8; i++)
#pragma unroll
            for (int j = 0; j < 8; j++) acc[i][j] = 0.f;

#pragma unroll 8
        for (int d = 0; d < 64; d++) {
            float4 qa = *(float4*)&Qs[d * 64 + 8 * ty];
            float4 qb = *(float4*)&Qs[d * 64 + 8 * ty + 4];
            float4 ka = *(float4*)&Ks[d * 128 + 8 * tx];
            float4 kb = *(float4*)&Ks[d * 128 + 8 * tx + 4];
            float qv[8] = {qa.x, qa.y, qa.z, qa.w, qb.x, qb.y, qb.z, qb.w};
            float kv[8] = {ka.x, ka.y, ka.z, ka.w, kb.x, kb.y, kb.z, kb.w};
#pragma unroll
            for (int i = 0; i < 8; i++)
#pragma unroll
                for (int j = 0; j < 8; j++) acc[i][j] += qv[i] * kv[j];
        }

        // online softmax per row (row r = 8*ty + i, spread over 16 tx lanes)
#pragma unroll
        for (int i = 0; i < 8; i++) {
            float mx = acc[i][0];
#pragma unroll
            for (int j = 1; j < 8; j++) mx = fmaxf(mx, acc[i][j]);
#pragma unroll
            for (int o = 8; o; o >>= 1)
                mx = fmaxf(mx, __shfl_xor_sync(0xffffffffu, mx, o));
            float mn = fmaxf(m[i], mx);
            float al = __expf(m[i] - mn);
            float rs = 0.f;
#pragma unroll
            for (int j = 0; j < 8; j++) {
                float p = __expf(acc[i][j] - mn);
                acc[i][j] = p;
                rs += p;
            }
#pragma unroll
            for (int o = 8; o; o >>= 1)
                rs += __shfl_xor_sync(0xffffffffu, rs, o);
            l[i] = l[i] * al + rs;
            m[i] = mn;
#pragma unroll
            for (int j = 0; j < 4; j++) O[i][j] *= al;
            *(float4*)&Ps[(8 * ty + i) * 128 + 8 * tx] =
                make_float4(acc[i][0], acc[i][1], acc[i][2], acc[i][3]);
            *(float4*)&Ps[(8 * ty + i) * 128 + 8 * tx + 4] =
                make_float4(acc[i][4], acc[i][5], acc[i][6], acc[i][7]);
        }
        __syncthreads();

        // O += P @ V   (process 4 keys per step, float4 P reads)
#pragma unroll 2
        for (int k4 = 0; k4 < 32; k4++) {
            int k = 4 * k4;
            float4 v0 = *(float4*)&Vs[(k + 0) * 64 + 4 * tx];
            float4 v1 = *(float4*)&Vs[(k + 1) * 64 + 4 * tx];
            float4 v2 = *(float4*)&Vs[(k + 2) * 64 + 4 * tx];
            float4 v3 = *(float4*)&Vs[(k + 3) * 64 + 4 * tx];
#pragma unroll
            for (int i = 0; i < 8; i++) {
                float4 p = *(float4*)&Ps[(8 * ty + i) * 128 + k];
                O[i][0] += p.x * v0.x + p.y * v1.x + p.z * v2.x + p.w * v3.x;
                O[i][1] += p.x * v0.y + p.y * v1.y + p.z * v2.y + p.w * v3.y;
                O[i][2] += p.x * v0.z + p.y * v1.z + p.z * v2.z + p.w * v3.z;
                O[i][3] += p.x * v0.w + p.y * v1.w + p.z * v2.w + p.w * v3.w;
            }
        }
    }

    // epilogue: out[b][n][h*64 + d] = O / l * (1/sqrt(E))
    int b = bh >> 3, h = bh & 7;
    const float inv = 0.04419417382415922f;  // 1/sqrt(512)
#pragma unroll
    for (int i = 0; i < 8; i++) {
        float s = inv / l[i];
        int n = q0 + 8 * ty + i;
        float4 o4 = make_float4(O[i][0] * s, O[i][1] * s, O[i][2] * s, O[i][3] * s);
        *(float4*)&out[((size_t)b * N_ + n) * E_ + h * 64 + 4 * tx] = o4;
    }
}

// ---------------- launch ------------------------------------------------------
extern "C" void kernel_launch(void* const* d_in, const int* in_sizes, int n_in,
                              void* d_out, int out_size) {
    const float* x  = (const float*)d_in[0];
    const float* Wk = (const float*)d_in[1];
    const float* bk = (const float*)d_in[2];
    const float* Wv = (const float*)d_in[3];
    const float* bv = (const float*)d_in[4];
    float* out = (float*)d_out;

    float *xT, *WkT, *WvT;
    cudaGetSymbolAddress((void**)&xT,  g_xT);
    cudaGetSymbolAddress((void**)&WkT, g_WkT);
    cudaGetSymbolAddress((void**)&WvT, g_WvT);

    cudaFuncSetAttribute(proj_kernel, cudaFuncAttributeMaxDynamicSharedMemorySize, 32768);
    cudaFuncSetAttribute(attn_kernel, cudaFuncAttributeMaxDynamicSharedMemorySize, 114688);

    // x: [b][n][e] -> xT [b][e][n]
    transpose_k<<<dim3(E_ / 32, N_ / 32, B_), dim3(32, 8)>>>(x, xT, N_, E_);
    // Wk/Wv: [hd][e] -> [e][hd]
    transpose_k<<<dim3(E_ / 32, E_ / 32, 1), dim3(32, 8)>>>(Wk, WkT, E_, E_);
    transpose_k<<<dim3(E_ / 32, E_ / 32, 1), dim3(32, 8)>>>(Wv, WvT, E_, E_);

    // K and V projections (z = 0 -> K, z = 1 -> V)
    proj_kernel<<<dim3(128, 8, 2), 128, 32768>>>(bk, bv);

    // attention: grid (query tiles, bh)
    attn_kernel<<<dim3(N_ / 64, BH_), 128, 114688>>>(out);
}

// round 5
// speedup vs baseline: 2.3549x; 2.3549x over previous
#include <cuda_runtime.h>
#include <math.h>
#include <cstdint>

// Problem constants
#define B_  4
#define N_  2048
#define E_  512
#define H_  8
#define D_  64
#define BH_ 32   // B_*H_

// ---------------- scratch (static __device__; no allocations allowed) -------
__device__ float g_xT   [B_ * E_ * N_];   // [b][e][n]
__device__ float g_WkT  [E_ * E_];        // [e][hd]
__device__ float g_WvT  [E_ * E_];        // [e][hd]
__device__ float g_K    [BH_ * N_ * D_];  // [bh][n][d]  keys, natural
__device__ float g_V    [BH_ * N_ * D_];  // [bh][n][d]  values, natural
__device__ float g_norm2[BH_ * N_];       // ||k||^2 per row
__device__ float g_gmax2[BH_];            // max ||k||^2 per bh

// ---------------- mma helpers (sm_80-era PTX, no 'a'-suffix features) --------
__device__ __forceinline__ void mma_tf32(float* d, const uint32_t* a,
                                         uint32_t b0, uint32_t b1) {
    asm volatile(
        "mma.sync.aligned.m16n8k8.row.col.f32.tf32.tf32.f32 "
        "{%0,%1,%2,%3}, {%4,%5,%6,%7}, {%8,%9}, {%0,%1,%2,%3};\n"
        : "+f"(d[0]), "+f"(d[1]), "+f"(d[2]), "+f"(d[3])
        : "r"(a[0]), "r"(a[1]), "r"(a[2]), "r"(a[3]), "r"(b0), "r"(b1));
}
__device__ __forceinline__ uint32_t f2tf(float x) {
    uint32_t r; asm("cvt.rna.tf32.f32 %0, %1;" : "=r"(r) : "f"(x)); return r;
}

// ---------------- transpose ---------------------------------------------------
__global__ void transpose_k(const float* __restrict__ src,
                            float* __restrict__ dst, int R, int C) {
    __shared__ float t[32][33];
    size_t off = (size_t)blockIdx.z * R * C;
    src += off; dst += off;
    int c0 = blockIdx.x * 32, r0 = blockIdx.y * 32;
#pragma unroll
    for (int i = threadIdx.y; i < 32; i += 8)
        t[i][threadIdx.x] = src[(size_t)(r0 + i) * C + c0 + threadIdx.x];
    __syncthreads();
#pragma unroll
    for (int i = threadIdx.y; i < 32; i += 8)
        dst[(size_t)(c0 + i) * R + r0 + threadIdx.x] = t[threadIdx.x][i];
}

// ---------------- K/V projection GEMM (SIMT fp32; K and V both natural) ------
__global__ void __launch_bounds__(128) proj_kernel(const float* __restrict__ bk,
                                                   const float* __restrict__ bv) {
    extern __shared__ float sm[];
    float* xs = sm;
    float* ws = sm + 64 * 64;

    int tid = threadIdx.x;
    int tx = tid & 15, ty = tid >> 4;
    int m0 = blockIdx.x * 64;
    int b  = m0 >> 11;
    int n0 = m0 & 2047;
    int h  = blockIdx.y;
    int c0 = h * 64;
    int z  = blockIdx.z;
    const float* WT = z ? g_WvT : g_WkT;

    float acc[8][4];
#pragma unroll
    for (int i = 0; i < 8; i++)
#pragma unroll
        for (int j = 0; j < 4; j++) acc[i][j] = 0.f;

    for (int ec = 0; ec < 8; ec++) {
        int e0 = ec * 64;
        __syncthreads();
#pragma unroll
        for (int it = 0; it < 8; it++) {
            int idx = it * 128 + tid;
            int e = idx >> 4, cc = idx & 15;
            *(float4*)&xs[e * 64 + cc * 4] =
                *(const float4*)&g_xT[((size_t)b * E_ + e0 + e) * N_ + n0 + cc * 4];
        }
#pragma unroll
        for (int it = 0; it < 8; it++) {
            int idx = it * 128 + tid;
            int e = idx >> 4, cc = idx & 15;
            *(float4*)&ws[e * 64 + cc * 4] =
                *(const float4*)&WT[(size_t)(e0 + e) * E_ + c0 + cc * 4];
        }
        __syncthreads();
#pragma unroll 8
        for (int e = 0; e < 64; e++) {
            float4 xa = *(float4*)&xs[e * 64 + 8 * ty];
            float4 xb = *(float4*)&xs[e * 64 + 8 * ty + 4];
            float4 w  = *(float4*)&ws[e * 64 + 4 * tx];
            float xv[8] = {xa.x, xa.y, xa.z, xa.w, xb.x, xb.y, xb.z, xb.w};
            float wv[4] = {w.x, w.y, w.z, w.w};
#pragma unroll
            for (int i = 0; i < 8; i++)
#pragma unroll
                for (int j = 0; j < 4; j++) acc[i][j] += xv[i] * wv[j];
        }
    }

    const float* bias = z ? bv : bk;
    float bb[4];
#pragma unroll
    for (int j = 0; j < 4; j++) bb[j] = bias[c0 + 4 * tx + j];

    int bh = b * 8 + h;
    float* dst = z ? g_V : g_K;
#pragma unroll
    for (int i = 0; i < 8; i++) {
        int n = n0 + 8 * ty + i;
        float4 v = make_float4(acc[i][0] + bb[0], acc[i][1] + bb[1],
                               acc[i][2] + bb[2], acc[i][3] + bb[3]);
        *(float4*)&dst[((size_t)bh * N_ + n) * 64 + 4 * tx] = v;
    }
}

// ---------------- row-norm kernel (static softmax max bound) -----------------
__global__ void __launch_bounds__(256) norm_kernel() {
    __shared__ float red[256];
    int bh = blockIdx.x, tid = threadIdx.x;
    const float* Kb = g_K + (size_t)bh * N_ * D_;
    float gm = 0.f;
    for (int r = tid; r < N_; r += 256) {
        const float4* p = (const float4*)(Kb + (size_t)r * D_);
        float s = 0.f;
#pragma unroll
        for (int j = 0; j < 16; j++) {
            float4 v = p[j];
            s += v.x * v.x + v.y * v.y + v.z * v.z + v.w * v.w;
        }
        g_norm2[bh * N_ + r] = s;
        gm = fmaxf(gm, s);
    }
    red[tid] = gm;
    __syncthreads();
    for (int o = 128; o; o >>= 1) {
        if (tid < o) red[tid] = fmaxf(red[tid], red[tid + o]);
        __syncthreads();
    }
    if (tid == 0) g_gmax2[bh] = red[0];
}

// ---------------- tf32 mma.sync flash attention -------------------------------
// CTA: 256 threads (8 warps), q-tile 128, key-tile 128, 16 tiles.
// Warp w owns q rows [16w, 16w+16). Static per-row max bound (norm product),
// so O accumulates in registers with no rescaling.
// SMEM (floats): Ks[128][76] tf32-bits | Vs[128][72] tf32-bits | P 8x[16][132]
#define KS_OFF 0
#define KS_STR 76
#define VS_OFF 9728
#define VS_STR 72
#define P_OFF  18944
#define P_STR  132
#define ATTN_SMEM 143360

__global__ void __launch_bounds__(256) attn_mma(float* __restrict__ out) {
    extern __shared__ float sm[];
    uint32_t* smu = (uint32_t*)sm;

    int tid = threadIdx.x;
    int w   = tid >> 5;
    int lane = tid & 31;
    int qq = lane & 3, g = lane >> 2;
    int q0 = blockIdx.x * 128;
    int bh = blockIdx.y;
    int b = bh >> 3, h = bh & 7;

    const float* Kb = g_K + (size_t)bh * N_ * D_;
    const float* Vb = g_V + (size_t)bh * N_ * D_;

    // Q fragments from gmem (L2-hot), cvt to tf32. Rows 16w+g / 16w+g+8.
    int qrow = q0 + 16 * w + g;
    uint32_t qf[8][4];
#pragma unroll
    for (int kk = 0; kk < 8; kk++) {
        qf[kk][0] = f2tf(Kb[(size_t)qrow * 64 + 8 * kk + qq]);
        qf[kk][1] = f2tf(Kb[(size_t)(qrow + 8) * 64 + 8 * kk + qq]);
        qf[kk][2] = f2tf(Kb[(size_t)qrow * 64 + 8 * kk + qq + 4]);
        qf[kk][3] = f2tf(Kb[(size_t)(qrow + 8) * 64 + 8 * kk + qq + 4]);
    }

    float gmax = g_gmax2[bh];
    float mhat0 = sqrtf(g_norm2[bh * N_ + qrow] * gmax);
    float mhat8 = sqrtf(g_norm2[bh * N_ + qrow + 8] * gmax);

    float oAcc[8][4];
#pragma unroll
    for (int i = 0; i < 8; i++)
#pragma unroll
        for (int j = 0; j < 4; j++) oAcc[i][j] = 0.f;
    float l0 = 0.f, l8 = 0.f;

    uint32_t* Pw = smu + P_OFF + w * (16 * P_STR);

    for (int t = 0; t < 16; t++) {
        int k0 = t * 128;
        __syncthreads();   // prev tile's readers done with Ks/Vs

        // fill K/V tiles (cvt to tf32 bits). 2048 float4 each / 256 threads.
#pragma unroll
        for (int it = 0; it < 8; it++) {
            int i = it * 256 + tid;
            int r = i >> 4, c = (i & 15) * 4;
            float4 kv = *(const float4*)&Kb[(size_t)(k0 + r) * 64 + c];
            uint32_t* dk = smu + KS_OFF + r * KS_STR + c;
            dk[0] = f2tf(kv.x); dk[1] = f2tf(kv.y);
            dk[2] = f2tf(kv.z); dk[3] = f2tf(kv.w);
            float4 vv = *(const float4*)&Vb[(size_t)(k0 + r) * 64 + c];
            uint32_t* dv = smu + VS_OFF + r * VS_STR + c;
            dv[0] = f2tf(vv.x); dv[1] = f2tf(vv.y);
            dv[2] = f2tf(vv.z); dv[3] = f2tf(vv.w);
        }
        __syncthreads();

        // ---- S = Q K^T : 16 n-tiles x 8 k-steps ----
        float sAcc[16][4];
#pragma unroll
        for (int nt = 0; nt < 16; nt++) {
#pragma unroll
            for (int j = 0; j < 4; j++) sAcc[nt][j] = 0.f;
#pragma unroll
            for (int kk = 0; kk < 8; kk++) {
                uint32_t b0 = smu[KS_OFF + (8 * nt + g) * KS_STR + 8 * kk + qq];
                uint32_t b1 = smu[KS_OFF + (8 * nt + g) * KS_STR + 8 * kk + qq + 4];
                mma_tf32(sAcc[nt], qf[kk], b0, b1);
            }
        }

        // ---- softmax: p = exp(s - mhat), accumulate l, stage P (tf32) ----
#pragma unroll
        for (int nt = 0; nt < 16; nt++) {
            float p0 = __expf(sAcc[nt][0] - mhat0);
            float p1 = __expf(sAcc[nt][1] - mhat0);
            float p2 = __expf(sAcc[nt][2] - mhat8);
            float p3 = __expf(sAcc[nt][3] - mhat8);
            l0 += p0 + p1;
            l8 += p2 + p3;
            uint2 u0 = make_uint2(f2tf(p0), f2tf(p1));
            uint2 u1 = make_uint2(f2tf(p2), f2tf(p3));
            *(uint2*)&Pw[g * P_STR + 8 * nt + 2 * qq] = u0;
            *(uint2*)&Pw[(g + 8) * P_STR + 8 * nt + 2 * qq] = u1;
        }
        __syncwarp();

        // ---- O += P V : 16 k-steps x 8 n-tiles (dims) ----
#pragma unroll
        for (int kk = 0; kk < 16; kk++) {
            uint32_t a[4];
            a[0] = Pw[g * P_STR + 8 * kk + qq];
            a[1] = Pw[(g + 8) * P_STR + 8 * kk + qq];
            a[2] = Pw[g * P_STR + 8 * kk + qq + 4];
            a[3] = Pw[(g + 8) * P_STR + 8 * kk + qq + 4];
#pragma unroll
            for (int nt = 0; nt < 8; nt++) {
                uint32_t b0 = smu[VS_OFF + (8 * kk + qq) * VS_STR + 8 * nt + g];
                uint32_t b1 = smu[VS_OFF + (8 * kk + qq + 4) * VS_STR + 8 * nt + g];
                mma_tf32(oAcc[nt], a, b0, b1);
            }
        }
    }

    // reduce l across the quad (lanes 4g..4g+3 share rows)
    l0 += __shfl_xor_sync(0xffffffffu, l0, 1);
    l0 += __shfl_xor_sync(0xffffffffu, l0, 2);
    l8 += __shfl_xor_sync(0xffffffffu, l8, 1);
    l8 += __shfl_xor_sync(0xffffffffu, l8, 2);

    const float inv = 0.04419417382415922f;   // 1/sqrt(512)
    float sc0 = inv / l0, sc8 = inv / l8;

    // out[b][n][h*64 + d]; thread holds rows qrow/qrow+8, cols 8nt+2qq+{0,1}
    float* op0 = out + ((size_t)b * N_ + qrow) * E_ + h * 64;
    float* op8 = out + ((size_t)b * N_ + qrow + 8) * E_ + h * 64;
#pragma unroll
    for (int nt = 0; nt < 8; nt++) {
        *(float2*)&op0[8 * nt + 2 * qq] = make_float2(oAcc[nt][0] * sc0, oAcc[nt][1] * sc0);
        *(float2*)&op8[8 * nt + 2 * qq] = make_float2(oAcc[nt][2] * sc8, oAcc[nt][3] * sc8);
    }
}

// ---------------- launch ------------------------------------------------------
extern "C" void kernel_launch(void* const* d_in, const int* in_sizes, int n_in,
                              void* d_out, int out_size) {
    const float* x  = (const float*)d_in[0];
    const float* Wk = (const float*)d_in[1];
    const float* bk = (const float*)d_in[2];
    const float* Wv = (const float*)d_in[3];
    const float* bv = (const float*)d_in[4];
    float* out = (float*)d_out;

    float *xT, *WkT, *WvT;
    cudaGetSymbolAddress((void**)&xT,  g_xT);
    cudaGetSymbolAddress((void**)&WkT, g_WkT);
    cudaGetSymbolAddress((void**)&WvT, g_WvT);

    cudaFuncSetAttribute(proj_kernel, cudaFuncAttributeMaxDynamicSharedMemorySize, 32768);
    cudaFuncSetAttribute(attn_mma,    cudaFuncAttributeMaxDynamicSharedMemorySize, ATTN_SMEM);

    transpose_k<<<dim3(E_ / 32, N_ / 32, B_), dim3(32, 8)>>>(x, xT, N_, E_);
    transpose_k<<<dim3(E_ / 32, E_ / 32, 1), dim3(32, 8)>>>(Wk, WkT, E_, E_);
    transpose_k<<<dim3(E_ / 32, E_ / 32, 1), dim3(32, 8)>>>(Wv, WvT, E_, E_);

    proj_kernel<<<dim3(128, 8, 2), 128, 32768>>>(bk, bv);

    norm_kernel<<<BH_, 256>>>();

    attn_mma<<<dim3(N_ / 128, BH_), 256, ATTN_SMEM>>>(out);
}

// round 6
// speedup vs baseline: 2.9823x; 1.2664x over previous
#include <cuda_runtime.h>
#include <math.h>
#include <cstdint>

// Problem constants
#define B_  4
#define N_  2048
#define E_  512
#define H_  8
#define D_  64
#define BH_ 32   // B_*H_

// ---------------- scratch (static __device__; no allocations allowed) -------
__device__ float g_K    [BH_ * N_ * D_];  // [bh][n][d]  keys, natural
__device__ float g_V    [BH_ * N_ * D_];  // [bh][n][d]  values, natural
__device__ float g_norm2[BH_ * N_];       // ||k||^2 per row
__device__ float g_gmax2[BH_];            // max ||k||^2 per bh

// ---------------- mma helpers (sm_80-era PTX, no 'a'-suffix features) --------
__device__ __forceinline__ void mma_tf32(float* d, const uint32_t* a,
                                         uint32_t b0, uint32_t b1) {
    asm volatile(
        "mma.sync.aligned.m16n8k8.row.col.f32.tf32.tf32.f32 "
        "{%0,%1,%2,%3}, {%4,%5,%6,%7}, {%8,%9}, {%0,%1,%2,%3};\n"
        : "+f"(d[0]), "+f"(d[1]), "+f"(d[2]), "+f"(d[3])
        : "r"(a[0]), "r"(a[1]), "r"(a[2]), "r"(a[3]), "r"(b0), "r"(b1));
}
__device__ __forceinline__ uint32_t f2tf(float x) {
    uint32_t r; asm("cvt.rna.tf32.f32 %0, %1;" : "=r"(r) : "f"(x)); return r;
}

// ---------------- K/V projection GEMM (tf32 mma.sync) ------------------------
// out[m, c] = sum_k x[m, k] * W[c, k] + bias[c];  m = token (b*2048+n), c = hd.
// CTA: 256 thr (8 warps). Tile 128m x 64c (c-tile == one head). 16 k-chunks of 32.
// smem strides == 12 (mod 32) -> fragment LDS is a perfect bank permutation.
#define PJ_STR 44
#define PJ_XS_OFF 0
#define PJ_WS_OFF (128 * PJ_STR)
#define PJ_SMEM ((128 * PJ_STR + 64 * PJ_STR) * 4)

__global__ void __launch_bounds__(256) proj_mma(const float* __restrict__ x,
                                                const float* __restrict__ Wk,
                                                const float* __restrict__ bk,
                                                const float* __restrict__ Wv,
                                                const float* __restrict__ bv) {
    extern __shared__ uint32_t smu[];
    int tid = threadIdx.x;
    int w = tid >> 5, lane = tid & 31;
    int qq = lane & 3, g = lane >> 2;
    int m0 = blockIdx.x * 128;
    int h  = blockIdx.y;          // head == 64-col tile
    int c0 = h * 64;
    int z  = blockIdx.z;
    const float* W    = z ? Wv : Wk;
    const float* bias = z ? bv : bk;
    float* dst        = z ? g_V : g_K;

    float acc[8][4];
#pragma unroll
    for (int i = 0; i < 8; i++)
#pragma unroll
        for (int j = 0; j < 4; j++) acc[i][j] = 0.f;

    for (int ec = 0; ec < 16; ec++) {
        int k0 = ec * 32;
        __syncthreads();
        // xs: 128 x 32 (4096 elems = 4 float4/thread)
#pragma unroll
        for (int it = 0; it < 4; it++) {
            int i = it * 256 + tid;
            int r = i >> 3, c4 = (i & 7) * 4;
            float4 v = *(const float4*)&x[(size_t)(m0 + r) * E_ + k0 + c4];
            uint32_t* d = smu + PJ_XS_OFF + r * PJ_STR + c4;
            d[0] = f2tf(v.x); d[1] = f2tf(v.y); d[2] = f2tf(v.z); d[3] = f2tf(v.w);
        }
        // ws: 64 x 32 (2048 elems = 2 float4/thread)
#pragma unroll
        for (int it = 0; it < 2; it++) {
            int i = it * 256 + tid;
            int r = i >> 3, c4 = (i & 7) * 4;
            float4 v = *(const float4*)&W[(size_t)(c0 + r) * E_ + k0 + c4];
            uint32_t* d = smu + PJ_WS_OFF + r * PJ_STR + c4;
            d[0] = f2tf(v.x); d[1] = f2tf(v.y); d[2] = f2tf(v.z); d[3] = f2tf(v.w);
        }
        __syncthreads();

        uint32_t af[4][4];
#pragma unroll
        for (int kk = 0; kk < 4; kk++) {
            const uint32_t* xr = smu + PJ_XS_OFF + (16 * w + g) * PJ_STR + 8 * kk + qq;
            af[kk][0] = xr[0];
            af[kk][1] = xr[8 * PJ_STR];
            af[kk][2] = xr[4];
            af[kk][3] = xr[8 * PJ_STR + 4];
        }
#pragma unroll
        for (int nt = 0; nt < 8; nt++) {
#pragma unroll
            for (int kk = 0; kk < 4; kk++) {
                uint32_t b0 = smu[PJ_WS_OFF + (8 * nt + g) * PJ_STR + 8 * kk + qq];
                uint32_t b1 = smu[PJ_WS_OFF + (8 * nt + g) * PJ_STR + 8 * kk + qq + 4];
                mma_tf32(acc[nt], af[kk], b0, b1);
            }
        }
    }

    // epilogue: rows m0+16w+g (+8), cols c0 + 8nt + 2qq (+1); dst[bh][n][d]
    int r0 = m0 + 16 * w + g;
    int b0i = r0 >> 11, n0i = r0 & 2047;
    int bh = b0i * 8 + h;
    float* p0 = dst + ((size_t)bh * N_ + n0i) * D_;
    float* p8 = p0 + 8 * D_;
#pragma unroll
    for (int nt = 0; nt < 8; nt++) {
        int c = 8 * nt + 2 * qq;
        float bb0 = bias[c0 + c], bb1 = bias[c0 + c + 1];
        *(float2*)&p0[c] = make_float2(acc[nt][0] + bb0, acc[nt][1] + bb1);
        *(float2*)&p8[c] = make_float2(acc[nt][2] + bb0, acc[nt][3] + bb1);
    }
}

// ---------------- row-norm kernel (static softmax max bound) -----------------
__global__ void __launch_bounds__(256) norm_kernel() {
    __shared__ float red[256];
    int bh = blockIdx.x, tid = threadIdx.x;
    const float* Kb = g_K + (size_t)bh * N_ * D_;
    float gm = 0.f;
    for (int r = tid; r < N_; r += 256) {
        const float4* p = (const float4*)(Kb + (size_t)r * D_);
        float s = 0.f;
#pragma unroll
        for (int j = 0; j < 16; j++) {
            float4 v = p[j];
            s += v.x * v.x + v.y * v.y + v.z * v.z + v.w * v.w;
        }
        g_norm2[bh * N_ + r] = s;
        gm = fmaxf(gm, s);
    }
    red[tid] = gm;
    __syncthreads();
    for (int o = 128; o; o >>= 1) {
        if (tid < o) red[tid] = fmaxf(red[tid], red[tid + o]);
        __syncthreads();
    }
    if (tid == 0) g_gmax2[bh] = red[0];
}

// ---------------- tf32 mma.sync flash attention -------------------------------
// CTA: 256 thr (8 warps), q-tile 128, key-tile 128, 16 tiles. Static per-row max
// (norm product) -> no online rescaling. P relayout C-frag -> A-frag via
// intra-quad shuffles (no smem). Fused per-nt: S-mma -> exp -> shuffle -> PV-mma.
// SMEM: Ks[128][76] + Vs[128][72] tf32-bits = 75776 B -> 2 CTAs/SM.
#define KS_OFF 0
#define KS_STR 76
#define VS_OFF 9728
#define VS_STR 72
#define ATTN_SMEM 75776

__global__ void __launch_bounds__(256, 2) attn_mma(float* __restrict__ out) {
    extern __shared__ uint32_t smu[];

    int tid = threadIdx.x;
    int w = tid >> 5, lane = tid & 31;
    int qq = lane & 3, g = lane >> 2;
    int quad = lane & 0x1C;
    int src1 = quad | (qq >> 1);
    int src2 = quad | ((qq >> 1) + 2);
    int q0 = blockIdx.x * 128;
    int bh = blockIdx.y;
    int b = bh >> 3, h = bh & 7;

    const float* Kb = g_K + (size_t)bh * N_ * D_;
    const float* Vb = g_V + (size_t)bh * N_ * D_;

    // Q fragments from gmem (L2-hot), cvt tf32. Rows 16w+g / +8.
    int qrow = q0 + 16 * w + g;
    uint32_t qf[8][4];
#pragma unroll
    for (int kk = 0; kk < 8; kk++) {
        qf[kk][0] = f2tf(Kb[(size_t)qrow * D_ + 8 * kk + qq]);
        qf[kk][1] = f2tf(Kb[(size_t)(qrow + 8) * D_ + 8 * kk + qq]);
        qf[kk][2] = f2tf(Kb[(size_t)qrow * D_ + 8 * kk + qq + 4]);
        qf[kk][3] = f2tf(Kb[(size_t)(qrow + 8) * D_ + 8 * kk + qq + 4]);
    }

    float gmax = g_gmax2[bh];
    float mhat0 = sqrtf(g_norm2[bh * N_ + qrow] * gmax);
    float mhat8 = sqrtf(g_norm2[bh * N_ + qrow + 8] * gmax);

    float oAcc[8][4];
#pragma unroll
    for (int i = 0; i < 8; i++)
#pragma unroll
        for (int j = 0; j < 4; j++) oAcc[i][j] = 0.f;
    float l0 = 0.f, l8 = 0.f;

    for (int t = 0; t < 16; t++) {
        int k0 = t * 128;
        __syncthreads();   // prev tile's MMAs done with Ks/Vs
#pragma unroll
        for (int it = 0; it < 8; it++) {
            int i = it * 256 + tid;
            int r = i >> 4, c = (i & 15) * 4;
            float4 kv = *(const float4*)&Kb[(size_t)(k0 + r) * D_ + c];
            uint32_t* dk = smu + KS_OFF + r * KS_STR + c;
            dk[0] = f2tf(kv.x); dk[1] = f2tf(kv.y);
            dk[2] = f2tf(kv.z); dk[3] = f2tf(kv.w);
            float4 vv = *(const float4*)&Vb[(size_t)(k0 + r) * D_ + c];
            uint32_t* dv = smu + VS_OFF + r * VS_STR + c;
            dv[0] = f2tf(vv.x); dv[1] = f2tf(vv.y);
            dv[2] = f2tf(vv.z); dv[3] = f2tf(vv.w);
        }
        __syncthreads();

#pragma unroll
        for (int nt = 0; nt < 16; nt++) {
            // ---- S(:, 8nt..8nt+7) = Q K^T ----
            float s[4] = {0.f, 0.f, 0.f, 0.f};
#pragma unroll
            for (int kk = 0; kk < 8; kk++) {
                uint32_t b0 = smu[KS_OFF + (8 * nt + g) * KS_STR + 8 * kk + qq];
                uint32_t b1 = smu[KS_OFF + (8 * nt + g) * KS_STR + 8 * kk + qq + 4];
                mma_tf32(s, qf[kk], b0, b1);
            }
            // ---- p = exp(s - mhat); accumulate l ----
            float p0 = __expf(s[0] - mhat0);
            float p1 = __expf(s[1] - mhat0);
            float p2 = __expf(s[2] - mhat8);
            float p3 = __expf(s[3] - mhat8);
            l0 += p0 + p1;
            l8 += p2 + p3;
            uint32_t c0v = f2tf(p0), c1v = f2tf(p1), c2v = f2tf(p2), c3v = f2tf(p3);
            // ---- C-frag -> A-frag relayout (intra-quad shuffles) ----
            uint32_t t0, t1, a[4];
            t0 = __shfl_sync(0xffffffffu, c0v, src1);
            t1 = __shfl_sync(0xffffffffu, c1v, src1);
            a[0] = (qq & 1) ? t1 : t0;
            t0 = __shfl_sync(0xffffffffu, c2v, src1);
            t1 = __shfl_sync(0xffffffffu, c3v, src1);
            a[1] = (qq & 1) ? t1 : t0;
            t0 = __shfl_sync(0xffffffffu, c0v, src2);
            t1 = __shfl_sync(0xffffffffu, c1v, src2);
            a[2] = (qq & 1) ? t1 : t0;
            t0 = __shfl_sync(0xffffffffu, c2v, src2);
            t1 = __shfl_sync(0xffffffffu, c3v, src2);
            a[3] = (qq & 1) ? t1 : t0;
            // ---- O += P(:, keys 8nt..8nt+7) @ V(rows 8nt..8nt+7, :) ----
#pragma unroll
            for (int vt = 0; vt < 8; vt++) {
                uint32_t b0 = smu[VS_OFF + (8 * nt + qq) * VS_STR + 8 * vt + g];
                uint32_t b1 = smu[VS_OFF + (8 * nt + qq + 4) * VS_STR + 8 * vt + g];
                mma_tf32(oAcc[vt], a, b0, b1);
            }
        }
    }

    // reduce l across the quad (lanes share rows)
    l0 += __shfl_xor_sync(0xffffffffu, l0, 1);
    l0 += __shfl_xor_sync(0xffffffffu, l0, 2);
    l8 += __shfl_xor_sync(0xffffffffu, l8, 1);
    l8 += __shfl_xor_sync(0xffffffffu, l8, 2);

    const float inv = 0.04419417382415922f;   // 1/sqrt(512)
    float sc0 = inv / l0, sc8 = inv / l8;

    float* op0 = out + ((size_t)b * N_ + qrow) * E_ + h * 64;
    float* op8 = out + ((size_t)b * N_ + qrow + 8) * E_ + h * 64;
#pragma unroll
    for (int vt = 0; vt < 8; vt++) {
        *(float2*)&op0[8 * vt + 2 * qq] = make_float2(oAcc[vt][0] * sc0, oAcc[vt][1] * sc0);
        *(float2*)&op8[8 * vt + 2 * qq] = make_float2(oAcc[vt][2] * sc8, oAcc[vt][3] * sc8);
    }
}

// ---------------- launch ------------------------------------------------------
extern "C" void kernel_launch(void* const* d_in, const int* in_sizes, int n_in,
                              void* d_out, int out_size) {
    const float* x  = (const float*)d_in[0];
    const float* Wk = (const float*)d_in[1];
    const float* bk = (const float*)d_in[2];
    const float* Wv = (const float*)d_in[3];
    const float* bv = (const float*)d_in[4];
    float* out = (float*)d_out;

    cudaFuncSetAttribute(proj_mma, cudaFuncAttributeMaxDynamicSharedMemorySize, PJ_SMEM);
    cudaFuncSetAttribute(attn_mma, cudaFuncAttributeMaxDynamicSharedMemorySize, ATTN_SMEM);

    // K and V projections straight from natural layouts (no transposes)
    proj_mma<<<dim3(64, 8, 2), 256, PJ_SMEM>>>(x, Wk, bk, Wv, bv);

    norm_kernel<<<BH_, 256>>>();

    attn_mma<<<dim3(N_ / 128, BH_), 256, ATTN_SMEM>>>(out);
}

// round 9
// speedup vs baseline: 3.4393x; 1.1532x over previous
#include <cuda_runtime.h>
#include <math.h>
#include <cstdint>

// Problem constants
#define B_  4
#define N_  2048
#define E_  512
#define H_  8
#define D_  64
#define BH_ 32   // B_*H_

// ---------------- scratch (static __device__; no allocations allowed) -------
__device__ float g_xr  [B_ * N_ * E_];    // x pre-rounded to tf32 grid
__device__ float g_Wkr [E_ * E_];
__device__ float g_Wvr [E_ * E_];
__device__ float g_K   [BH_ * N_ * D_];   // keys, natural, tf32-rounded
__device__ float g_V   [BH_ * N_ * D_];   // values, natural, tf32-rounded
__device__ float g_norm2[BH_ * N_];
__device__ float g_gmax2[BH_];

// ---------------- helpers (sm_80-era PTX only) --------------------------------
__device__ __forceinline__ void mma_tf32(float* d, const uint32_t* a,
                                         uint32_t b0, uint32_t b1) {
    asm volatile(
        "mma.sync.aligned.m16n8k8.row.col.f32.tf32.tf32.f32 "
        "{%0,%1,%2,%3}, {%4,%5,%6,%7}, {%8,%9}, {%0,%1,%2,%3};\n"
        : "+f"(d[0]), "+f"(d[1]), "+f"(d[2]), "+f"(d[3])
        : "r"(a[0]), "r"(a[1]), "r"(a[2]), "r"(a[3]), "r"(b0), "r"(b1));
}
__device__ __forceinline__ uint32_t f2tf(float x) {
    uint32_t r; asm("cvt.rna.tf32.f32 %0, %1;" : "=r"(r) : "f"(x)); return r;
}
__device__ __forceinline__ uint32_t smem_u32(const void* p) {
    uint32_t a;
    asm("{ .reg .u64 t; cvta.to.shared.u64 t, %1; cvt.u32.u64 %0, t; }"
        : "=r"(a) : "l"(p));
    return a;
}
#define CP16(dst, src) \
    asm volatile("cp.async.cg.shared.global [%0], [%1], 16;" :: "r"(dst), "l"(src) : "memory")
#define CP_COMMIT() asm volatile("cp.async.commit_group;" ::: "memory")
#define CP_WAIT(n)  asm volatile("cp.async.wait_group %0;" :: "n"(n) : "memory")

// ---------------- pre-round to tf32-representable fp32 -----------------------
__global__ void round_kernel(const float* __restrict__ src,
                             float* __restrict__ dst, int n4) {
    int i = blockIdx.x * 256 + threadIdx.x;
    if (i >= n4) return;
    float4 v = *(const float4*)(src + 4 * i);
    v.x = __uint_as_float(f2tf(v.x));
    v.y = __uint_as_float(f2tf(v.y));
    v.z = __uint_as_float(f2tf(v.z));
    v.w = __uint_as_float(f2tf(v.w));
    *(float4*)(dst + 4 * i) = v;
}

// ---------------- K/V projection GEMM (tf32 mma, cp.async double-buffer) ----
// Tile 128m x 64c (one head per y), z: 0=K, 1=V. 16 k-chunks of 32, 2-stage.
// smem strides 44 (mod 32 == 12) -> conflict-free fragment LDS, 16B-aligned rows.
#define PJ_STR 44
#define PJ_BUF (128 * PJ_STR + 64 * PJ_STR)   // floats per stage: 8448
#define PJ_WOF (128 * PJ_STR)
#define PJ_SMEM (2 * PJ_BUF * 4)              // 67584 B

__device__ __forceinline__ void pj_issue(uint32_t sb, int stage, int k0,
                                         const float* __restrict__ x,
                                         const float* __restrict__ W,
                                         int m0, int c0, int tid) {
    uint32_t base = sb + stage * (PJ_BUF * 4);
#pragma unroll
    for (int it = 0; it < 4; it++) {           // xs: 1024 16B chunks
        int i = it * 256 + tid;
        int r = i >> 3, c4 = (i & 7) * 4;
        CP16(base + (r * PJ_STR + c4) * 4,
             x + (size_t)(m0 + r) * E_ + k0 + c4);
    }
#pragma unroll
    for (int it = 0; it < 2; it++) {           // ws: 512 16B chunks
        int i = it * 256 + tid;
        int r = i >> 3, c4 = (i & 7) * 4;
        CP16(base + (PJ_WOF + r * PJ_STR + c4) * 4,
             W + (size_t)(c0 + r) * E_ + k0 + c4);
    }
    CP_COMMIT();
}

__global__ void __launch_bounds__(256) proj_mma(const float* __restrict__ bk,
                                                const float* __restrict__ bv) {
    extern __shared__ uint32_t smu[];
    uint32_t sb = smem_u32(smu);
    int tid = threadIdx.x;
    int w = tid >> 5, lane = tid & 31;
    int qq = lane & 3, g = lane >> 2;
    int m0 = blockIdx.x * 128;
    int h  = blockIdx.y;
    int c0 = h * 64;
    int z  = blockIdx.z;
    const float* x    = g_xr;
    const float* W    = z ? g_Wvr : g_Wkr;
    const float* bias = z ? bv : bk;
    float* dst        = z ? g_V : g_K;

    float acc[8][4];
#pragma unroll
    for (int i = 0; i < 8; i++)
#pragma unroll
        for (int j = 0; j < 4; j++) acc[i][j] = 0.f;

    pj_issue(sb, 0, 0, x, W, m0, c0, tid);

    for (int ec = 0; ec < 16; ec++) {
        if (ec < 15) pj_issue(sb, (ec + 1) & 1, (ec + 1) * 32, x, W, m0, c0, tid);
        if (ec < 15) { CP_WAIT(1); } else { CP_WAIT(0); }
        __syncthreads();

        const uint32_t* bf = smu + (ec & 1) * PJ_BUF;
        uint32_t af[4][4];
#pragma unroll
        for (int kk = 0; kk < 4; kk++) {
            const uint32_t* xr = bf + (16 * w + g) * PJ_STR + 8 * kk + qq;
            af[kk][0] = xr[0];
            af[kk][1] = xr[8 * PJ_STR];
            af[kk][2] = xr[4];
            af[kk][3] = xr[8 * PJ_STR + 4];
        }
#pragma unroll
        for (int nt = 0; nt < 8; nt++) {
#pragma unroll
            for (int kk = 0; kk < 4; kk++) {
                uint32_t b0 = bf[PJ_WOF + (8 * nt + g) * PJ_STR + 8 * kk + qq];
                uint32_t b1 = bf[PJ_WOF + (8 * nt + g) * PJ_STR + 8 * kk + qq + 4];
                mma_tf32(acc[nt], af[kk], b0, b1);
            }
        }
        __syncthreads();
    }

    // epilogue: add bias, round to tf32 grid, store
    int r0 = m0 + 16 * w + g;
    int b0i = r0 >> 11, n0i = r0 & 2047;
    int bh = b0i * 8 + h;
    float* p0 = dst + ((size_t)bh * N_ + n0i) * D_;
    float* p8 = p0 + 8 * D_;
#pragma unroll
    for (int nt = 0; nt < 8; nt++) {
        int c = 8 * nt + 2 * qq;
        float bb0 = bias[c0 + c], bb1 = bias[c0 + c + 1];
        *(float2*)&p0[c] = make_float2(__uint_as_float(f2tf(acc[nt][0] + bb0)),
                                       __uint_as_float(f2tf(acc[nt][1] + bb1)));
        *(float2*)&p8[c] = make_float2(__uint_as_float(f2tf(acc[nt][2] + bb0)),
                                       __uint_as_float(f2tf(acc[nt][3] + bb1)));
    }
}

// ---------------- row-norm kernel (static softmax max bound) -----------------
__global__ void __launch_bounds__(256) norm_kernel() {
    __shared__ float red[256];
    int bh = blockIdx.x, tid = threadIdx.x;
    const float* Kb = g_K + (size_t)bh * N_ * D_;
    float gm = 0.f;
    for (int r = tid; r < N_; r += 256) {
        const float4* p = (const float4*)(Kb + (size_t)r * D_);
        float s = 0.f;
#pragma unroll
        for (int j = 0; j < 16; j++) {
            float4 v = p[j];
            s += v.x * v.x + v.y * v.y + v.z * v.z + v.w * v.w;
        }
        g_norm2[bh * N_ + r] = s;
        gm = fmaxf(gm, s);
    }
    red[tid] = gm;
    __syncthreads();
    for (int o = 128; o; o >>= 1) {
        if (tid < o) red[tid] = fmaxf(red[tid], red[tid + o]);
        __syncthreads();
    }
    if (tid == 0) g_gmax2[bh] = red[0];
}

// ---------------- tf32 mma flash attention (cp.async double-buffer) ----------
// CTA: 256 thr (8 warps), q-tile 128, key-tile 64, 32 tiles, 2-stage pipeline.
// Static per-row max bound -> no rescaling; P relayout via intra-quad shuffles.
// SMEM: 2 x (Ks[64][76] + Vs[64][72]) = 75776 B -> 2 CTAs/SM.
#define KS_STR 76
#define VS_STR 72
#define AT_VOF (64 * KS_STR)                  // 4864 floats
#define AT_BUF (64 * KS_STR + 64 * VS_STR)    // 9472 floats per stage
#define ATTN_SMEM (2 * AT_BUF * 4)            // 75776 B

__device__ __forceinline__ void at_issue(uint32_t sb, int stage, int k0,
                                         const float* __restrict__ Kb,
                                         const float* __restrict__ Vb, int tid) {
    uint32_t base = sb + stage * (AT_BUF * 4);
#pragma unroll
    for (int it = 0; it < 4; it++) {          // Ks: 1024 16B chunks
        int i = it * 256 + tid;
        int r = i >> 4, c4 = (i & 15) * 4;
        CP16(base + (r * KS_STR + c4) * 4,
             Kb + (size_t)(k0 + r) * D_ + c4);
    }
#pragma unroll
    for (int it = 0; it < 4; it++) {          // Vs: 1024 16B chunks
        int i = it * 256 + tid;
        int r = i >> 4, c4 = (i & 15) * 4;
        CP16(base + (AT_VOF + r * VS_STR + c4) * 4,
             Vb + (size_t)(k0 + r) * D_ + c4);
    }
    CP_COMMIT();
}

__global__ void __launch_bounds__(256, 2) attn_mma(float* __restrict__ out) {
    extern __shared__ uint32_t smu[];
    uint32_t sb = smem_u32(smu);

    int tid = threadIdx.x;
    int w = tid >> 5, lane = tid & 31;
    int qq = lane & 3, g = lane >> 2;
    int quad = lane & 0x1C;
    int src1 = quad | (qq >> 1);
    int src2 = quad | ((qq >> 1) + 2);
    int q0 = blockIdx.x * 128;
    int bh = blockIdx.y;
    int b = bh >> 3, h = bh & 7;

    const float* Kb = g_K + (size_t)bh * N_ * D_;
    const float* Vb = g_V + (size_t)bh * N_ * D_;

    // Q fragments (values already tf32-rounded -> raw bit loads, no cvt)
    int qrow = q0 + 16 * w + g;
    const uint32_t* Ku = (const uint32_t*)Kb;
    uint32_t qf[8][4];
#pragma unroll
    for (int kk = 0; kk < 8; kk++) {
        qf[kk][0] = Ku[(size_t)qrow * D_ + 8 * kk + qq];
        qf[kk][1] = Ku[(size_t)(qrow + 8) * D_ + 8 * kk + qq];
        qf[kk][2] = Ku[(size_t)qrow * D_ + 8 * kk + qq + 4];
        qf[kk][3] = Ku[(size_t)(qrow + 8) * D_ + 8 * kk + qq + 4];
    }

    float gmax = g_gmax2[bh];
    float mhat0 = sqrtf(g_norm2[bh * N_ + qrow] * gmax);
    float mhat8 = sqrtf(g_norm2[bh * N_ + qrow + 8] * gmax);

    float oAcc[8][4];
#pragma unroll
    for (int i = 0; i < 8; i++)
#pragma unroll
        for (int j = 0; j < 4; j++) oAcc[i][j] = 0.f;
    float l0 = 0.f, l8 = 0.f;

    at_issue(sb, 0, 0, Kb, Vb, tid);

    for (int t = 0; t < 32; t++) {
        if (t < 31) at_issue(sb, (t + 1) & 1, (t + 1) * 64, Kb, Vb, tid);
        if (t < 31) { CP_WAIT(1); } else { CP_WAIT(0); }
        __syncthreads();

        const uint32_t* Ksb = smu + (t & 1) * AT_BUF;
        const uint32_t* Vsb = Ksb + AT_VOF;

#pragma unroll
        for (int nt = 0; nt < 8; nt++) {
            // ---- S(:, 8nt..8nt+7) = Q K^T (two 4-deep chains) ----
            float sA[4] = {0.f, 0.f, 0.f, 0.f};
            float sB[4] = {0.f, 0.f, 0.f, 0.f};
#pragma unroll
            for (int kk = 0; kk < 4; kk++) {
                uint32_t b0 = Ksb[(8 * nt + g) * KS_STR + 8 * kk + qq];
                uint32_t b1 = Ksb[(8 * nt + g) * KS_STR + 8 * kk + qq + 4];
                mma_tf32(sA, qf[kk], b0, b1);
            }
#pragma unroll
            for (int kk = 4; kk < 8; kk++) {
                uint32_t b0 = Ksb[(8 * nt + g) * KS_STR + 8 * kk + qq];
                uint32_t b1 = Ksb[(8 * nt + g) * KS_STR + 8 * kk + qq + 4];
                mma_tf32(sB, qf[kk], b0, b1);
            }
            // ---- p = exp(s - mhat); accumulate l ----
            float p0 = __expf(sA[0] + sB[0] - mhat0);
            float p1 = __expf(sA[1] + sB[1] - mhat0);
            float p2 = __expf(sA[2] + sB[2] - mhat8);
            float p3 = __expf(sA[3] + sB[3] - mhat8);
            l0 += p0 + p1;
            l8 += p2 + p3;
            uint32_t c0v = f2tf(p0), c1v = f2tf(p1), c2v = f2tf(p2), c3v = f2tf(p3);
            // ---- C-frag -> A-frag relayout (intra-quad shuffles) ----
            uint32_t t0, t1, a[4];
            t0 = __shfl_sync(0xffffffffu, c0v, src1);
            t1 = __shfl_sync(0xffffffffu, c1v, src1);
            a[0] = (qq & 1) ? t1 : t0;
            t0 = __shfl_sync(0xffffffffu, c2v, src1);
            t1 = __shfl_sync(0xffffffffu, c3v, src1);
            a[1] = (qq & 1) ? t1 : t0;
            t0 = __shfl_sync(0xffffffffu, c0v, src2);
            t1 = __shfl_sync(0xffffffffu, c1v, src2);
            a[2] = (qq & 1) ? t1 : t0;
            t0 = __shfl_sync(0xffffffffu, c2v, src2);
            t1 = __shfl_sync(0xffffffffu, c3v, src2);
            a[3] = (qq & 1) ? t1 : t0;
            // ---- O += P V ----
#pragma unroll
            for (int vt = 0; vt < 8; vt++) {
                uint32_t b0 = Vsb[(8 * nt + qq) * VS_STR + 8 * vt + g];
                uint32_t b1 = Vsb[(8 * nt + qq + 4) * VS_STR + 8 * vt + g];
                mma_tf32(oAcc[vt], a, b0, b1);
            }
        }
        __syncthreads();
    }

    // reduce l across the quad
    l0 += __shfl_xor_sync(0xffffffffu, l0, 1);
    l0 += __shfl_xor_sync(0xffffffffu, l0, 2);
    l8 += __shfl_xor_sync(0xffffffffu, l8, 1);
    l8 += __shfl_xor_sync(0xffffffffu, l8, 2);

    const float inv = 0.04419417382415922f;   // 1/sqrt(512)
    float sc0 = inv / l0, sc8 = inv / l8;

    float* op0 = out + ((size_t)b * N_ + qrow) * E_ + h * 64;
    float* op8 = out + ((size_t)b * N_ + qrow + 8) * E_ + h * 64;
#pragma unroll
    for (int vt = 0; vt < 8; vt++) {
        *(float2*)&op0[8 * vt + 2 * qq] = make_float2(oAcc[vt][0] * sc0, oAcc[vt][1] * sc0);
        *(float2*)&op8[8 * vt + 2 * qq] = make_float2(oAcc[vt][2] * sc8, oAcc[vt][3] * sc8);
    }
}

// ---------------- launch ------------------------------------------------------
extern "C" void kernel_launch(void* const* d_in, const int* in_sizes, int n_in,
                              void* d_out, int out_size) {
    const float* x  = (const float*)d_in[0];
    const float* Wk = (const float*)d_in[1];
    const float* bk = (const float*)d_in[2];
    const float* Wv = (const float*)d_in[3];
    const float* bv = (const float*)d_in[4];
    float* out = (float*)d_out;

    float *xr, *Wkr, *Wvr;
    cudaGetSymbolAddress((void**)&xr,  g_xr);
    cudaGetSymbolAddress((void**)&Wkr, g_Wkr);
    cudaGetSymbolAddress((void**)&Wvr, g_Wvr);

    cudaFuncSetAttribute(proj_mma, cudaFuncAttributeMaxDynamicSharedMemorySize, PJ_SMEM);
    cudaFuncSetAttribute(attn_mma, cudaFuncAttributeMaxDynamicSharedMemorySize, ATTN_SMEM);

    // pre-round inputs to tf32-representable fp32 (enables raw cp.async later)
    round_kernel<<<(B_ * N_ * E_ / 4 + 255) / 256, 256>>>(x, xr, B_ * N_ * E_ / 4);
    round_kernel<<<(E_ * E_ / 4 + 255) / 256, 256>>>(Wk, Wkr, E_ * E_ / 4);
    round_kernel<<<(E_ * E_ / 4 + 255) / 256, 256>>>(Wv, Wvr, E_ * E_ / 4);

    proj_mma<<<dim3(64, 8, 2), 256, PJ_SMEM>>>(bk, bv);

    norm_kernel<<<BH_, 256>>>();

    attn_mma<<<dim3(N_ / 128, BH_), 256, ATTN_SMEM>>>(out);
}